// round 15
// baseline (speedup 1.0000x reference)
#include <cuda_runtime.h>
#include <cuda_fp16.h>

// ---------------------------------------------------------------------------
// GCN link prediction, CSR-gather formulation.
//   layer1: hs1 = dinv*(x@W1) (fp16, scaled by k_scale after gemm1||build)
//   agg1-fused: acc = hs1[c] + sum hs1[src]; h1 = relu(dinv*acc + b1) kept in
//     REGISTERS; warp-GEMM h2 = h1@W2 (W2 in smem, shfl broadcast);
//     bufB = fp16(dinv*h2).   <-- gemm2 kernel + fp32 bufC eliminated
//   agg2: acc = bufB[c] + sum bufB[src]; z = fp16(dinv*acc + b2)
//   decode: dot64 over fp16 z.
// ---------------------------------------------------------------------------

#define N_NODES 50000
#define E_TRAIN 1600000
#define EP      200000
#define EN      200000
#define F_IN    50
#define HID     50
#define DOUT    64
#define PAD     64

#define SCAN_B  1024
#define SCAN_NBLK ((N_NODES + SCAN_B - 1) / SCAN_B)   // 49

__device__ __align__(256) __half g_bufA[N_NODES * PAD]; // hs1 fp16 (layer-1 gather src)
__device__ __align__(256) __half g_bufB[N_NODES * PAD]; // hs2 fp16 (layer-2 gather src)
__device__ __align__(256) __half g_z[N_NODES * PAD];    // final z (fp16)
__device__ int   g_deg[N_NODES];
__device__ int   g_rowptr[N_NODES + 1];
__device__ int   g_bsum[SCAN_NBLK];
__device__ int   g_boff[SCAN_NBLK];
__device__ __align__(16) unsigned short g_rank[E_TRAIN];
__device__ __align__(16) unsigned short g_esrc[E_TRAIN];
__device__ float g_dinv[N_NODES];

// ---- degree + rank ----------------------------------------------------------
__global__ void k_zero() {
    int i = blockIdx.x * blockDim.x + threadIdx.x;
    if (i < N_NODES) g_deg[i] = 0;
}

__global__ void k_count(const int* __restrict__ dst) {
    int t = blockIdx.x * 256 + threadIdx.x;
    if (t < E_TRAIN / 8) {
        int4 d0 = __ldg((const int4*)dst + 2 * t);
        int4 d1 = __ldg((const int4*)dst + 2 * t + 1);
        unsigned r0 = atomicAdd(&g_deg[d0.x], 1);
        unsigned r1 = atomicAdd(&g_deg[d0.y], 1);
        unsigned r2 = atomicAdd(&g_deg[d0.z], 1);
        unsigned r3 = atomicAdd(&g_deg[d0.w], 1);
        unsigned r4 = atomicAdd(&g_deg[d1.x], 1);
        unsigned r5 = atomicAdd(&g_deg[d1.y], 1);
        unsigned r6 = atomicAdd(&g_deg[d1.z], 1);
        unsigned r7 = atomicAdd(&g_deg[d1.w], 1);
        uint4 pk;
        pk.x = r0 | (r1 << 16);
        pk.y = r2 | (r3 << 16);
        pk.z = r4 | (r5 << 16);
        pk.w = r6 | (r7 << 16);
        ((uint4*)g_rank)[t] = pk;
    }
}

// ---- 3-phase multi-block exclusive scan -> rowptr/dinv ----------------------
__global__ __launch_bounds__(SCAN_B) void k_scan_local() {
    __shared__ int sh[SCAN_B];
    int t = threadIdx.x;
    int gid = blockIdx.x * SCAN_B + t;
    int d = (gid < N_NODES) ? g_deg[gid] : 0;
    int val = d;
    sh[t] = val;
    __syncthreads();
    for (int off = 1; off < SCAN_B; off <<= 1) {
        int v = (t >= off) ? sh[t - off] : 0;
        __syncthreads();
        val += v;
        sh[t] = val;
        __syncthreads();
    }
    if (gid < N_NODES) {
        g_rowptr[gid] = val - d;
        g_dinv[gid]   = rsqrtf((float)(d + 1));  // +1 self loop
    }
    if (t == SCAN_B - 1) g_bsum[blockIdx.x] = val;
}

__global__ void k_scan_bsum() {
    __shared__ int sh[SCAN_NBLK];
    int t = threadIdx.x;   // 64 threads
    if (t < SCAN_NBLK) sh[t] = g_bsum[t];
    __syncthreads();
    if (t == 0) {
        int run = 0;
#pragma unroll
        for (int i = 0; i < SCAN_NBLK; i++) {
            int d = sh[i];
            sh[i] = run;
            run += d;
        }
        g_rowptr[N_NODES] = run;
    }
    __syncthreads();
    if (t < SCAN_NBLK) g_boff[t] = sh[t];
}

__global__ __launch_bounds__(SCAN_B) void k_scan_add() {
    int gid = blockIdx.x * SCAN_B + threadIdx.x;
    if (gid < N_NODES) g_rowptr[gid] += __ldg(g_boff + blockIdx.x);
}

// ---- atomic-free placement (4 edges/thread) ---------------------------------
__global__ void k_place(const int* __restrict__ src, const int* __restrict__ dst) {
    int t = blockIdx.x * 256 + threadIdx.x;
    if (t < E_TRAIN / 4) {
        int4 s0 = __ldg((const int4*)src + t);
        int4 d0 = __ldg((const int4*)dst + t);
        uint2 pk = __ldg((const uint2*)g_rank + t);
        int p0 = __ldg(g_rowptr + d0.x) + (pk.x & 0xffff);
        int p1 = __ldg(g_rowptr + d0.y) + (pk.x >> 16);
        int p2 = __ldg(g_rowptr + d0.z) + (pk.y & 0xffff);
        int p3 = __ldg(g_rowptr + d0.w) + (pk.y >> 16);
        g_esrc[p0] = (unsigned short)s0.x;
        g_esrc[p1] = (unsigned short)s0.y;
        g_esrc[p2] = (unsigned short)s0.z;
        g_esrc[p3] = (unsigned short)s0.w;
    }
}

// ---- scale bufA rows by dinv (layer 1) --------------------------------------
__global__ __launch_bounds__(256) void k_scale() {
    int t = blockIdx.x * 256 + threadIdx.x;   // 3125 blocks exact
    int node = t >> 4, q = t & 15;
    float di = __ldg(g_dinv + node);
    uint2 u = *(uint2*)&g_bufA[node * PAD + q * 4];
    __half2* hp = (__half2*)&u;
    float2 f0 = __half22float2(hp[0]);
    float2 f1 = __half22float2(hp[1]);
    __half2 o0 = __floats2half2_rn(f0.x * di, f0.y * di);
    __half2 o1 = __floats2half2_rn(f1.x * di, f1.y * di);
    uint2 st; st.x = *(unsigned*)&o0; st.y = *(unsigned*)&o1;
    *(uint2*)&g_bufA[node * PAD + q * 4] = st;
}

// ---- GEMM 1: bufA = fp16(x @ W1) UNSCALED, 32 nodes/block -------------------
__global__ __launch_bounds__(256) void k_gemm1(const float* __restrict__ x,
                                               const float* __restrict__ W1) {
    __shared__ float ws[F_IN][64];
    __shared__ float xs[32][F_IN + 2];
    int tid = threadIdx.x;
    int nodeBase = blockIdx.x * 32;
    for (int t = tid; t < F_IN * 64; t += 256) {
        int k = t >> 6, j = t & 63;
        ws[k][j] = (j < HID) ? W1[k * HID + j] : 0.f;
    }
    for (int t = tid; t < 32 * F_IN; t += 256) {
        int n = t / F_IN, k = t % F_IN;
        int node = nodeBase + n;
        xs[n][k] = (node < N_NODES) ? x[node * F_IN + k] : 0.f;
    }
    __syncthreads();
    int n = tid >> 4, jq = tid & 15;
    int node0 = nodeBase + n;
    int node1 = nodeBase + n + 16;
    float4 accA = make_float4(0.f, 0.f, 0.f, 0.f);
    float4 accB = make_float4(0.f, 0.f, 0.f, 0.f);
#pragma unroll
    for (int k = 0; k < F_IN; k++) {
        float4 w = *(const float4*)&ws[k][jq * 4];
        float xv0 = xs[n][k];
        float xv1 = xs[n + 16][k];
        accA.x = fmaf(xv0, w.x, accA.x);
        accA.y = fmaf(xv0, w.y, accA.y);
        accA.z = fmaf(xv0, w.z, accA.z);
        accA.w = fmaf(xv0, w.w, accA.w);
        accB.x = fmaf(xv1, w.x, accB.x);
        accB.y = fmaf(xv1, w.y, accB.y);
        accB.z = fmaf(xv1, w.z, accB.z);
        accB.w = fmaf(xv1, w.w, accB.w);
    }
    if (node0 < N_NODES) {
        __half2 p0 = __floats2half2_rn(accA.x, accA.y);
        __half2 p1 = __floats2half2_rn(accA.z, accA.w);
        uint2 st; st.x = *(unsigned*)&p0; st.y = *(unsigned*)&p1;
        *(uint2*)&g_bufA[node0 * PAD + jq * 4] = st;
    }
    if (node1 < N_NODES) {
        __half2 p0 = __floats2half2_rn(accB.x, accB.y);
        __half2 p1 = __floats2half2_rn(accB.z, accB.w);
        uint2 st; st.x = *(unsigned*)&p0; st.y = *(unsigned*)&p1;
        *(uint2*)&g_bufA[node1 * PAD + jq * 4] = st;
    }
}

// ---- common gather body: accumulate chunk (lane&7) of node's CSR sum --------
// After RED(8)+RED(16), ALL lanes hold the full reduced sums for their chunk.
#define GATHER_BODY(ROWS, CH)                                               \
    int lane = threadIdx.x & 31;                                            \
    int g = lane >> 3, q = lane & 7;                                        \
    int rp = g_rowptr[node], re = g_rowptr[node + 1];                       \
    float a0 = 0.f, a1 = 0.f, a2 = 0.f, a3 = 0.f;                           \
    float a4 = 0.f, a5 = 0.f, a6 = 0.f, a7 = 0.f;                           \
    const uint4* rows = (const uint4*)(ROWS);                               \
    const bool act = ((CH) == 8) || (q < (CH));                             \
    if (g == 0 && act) {                                                    \
        uint4 u = __ldg(rows + node * 8 + q);                               \
        ACCUM(u);                                                           \
    }                                                                       \
    int e = rp + g;                                                         \
    for (; e + 12 < re; e += 16) {                                          \
        int s0 = (int)__ldg(g_esrc + e);                                    \
        int s1 = (int)__ldg(g_esrc + e + 4);                                \
        int s2 = (int)__ldg(g_esrc + e + 8);                                \
        int s3 = (int)__ldg(g_esrc + e + 12);                               \
        if (act) {                                                          \
            uint4 u0 = __ldg(rows + s0 * 8 + q);                            \
            uint4 u1 = __ldg(rows + s1 * 8 + q);                            \
            uint4 u2 = __ldg(rows + s2 * 8 + q);                            \
            uint4 u3 = __ldg(rows + s3 * 8 + q);                            \
            ACCUM(u0); ACCUM(u1); ACCUM(u2); ACCUM(u3);                     \
        }                                                                   \
    }                                                                       \
    for (; e + 4 < re; e += 8) {                                            \
        int s0 = (int)__ldg(g_esrc + e);                                    \
        int s1 = (int)__ldg(g_esrc + e + 4);                                \
        if (act) {                                                          \
            uint4 u0 = __ldg(rows + s0 * 8 + q);                            \
            uint4 u1 = __ldg(rows + s1 * 8 + q);                            \
            ACCUM(u0); ACCUM(u1);                                           \
        }                                                                   \
    }                                                                       \
    if (e < re) {                                                           \
        int s0 = (int)__ldg(g_esrc + e);                                    \
        if (act) {                                                          \
            uint4 u0 = __ldg(rows + s0 * 8 + q);                            \
            ACCUM(u0);                                                      \
        }                                                                   \
    }                                                                       \
    RED(8);                                                                 \
    RED(16);

#define ACCUM(U) do {                                                   \
        __half2* hp = (__half2*)&(U);                                   \
        float2 f0 = __half22float2(hp[0]);                              \
        float2 f1 = __half22float2(hp[1]);                              \
        float2 f2 = __half22float2(hp[2]);                              \
        float2 f3 = __half22float2(hp[3]);                              \
        a0 += f0.x; a1 += f0.y; a2 += f1.x; a3 += f1.y;                 \
        a4 += f2.x; a5 += f2.y; a6 += f3.x; a7 += f3.y;                 \
    } while (0)

#define RED(off) do {                                                   \
        a0 += __shfl_xor_sync(0xffffffffu, a0, off);                    \
        a1 += __shfl_xor_sync(0xffffffffu, a1, off);                    \
        a2 += __shfl_xor_sync(0xffffffffu, a2, off);                    \
        a3 += __shfl_xor_sync(0xffffffffu, a3, off);                    \
        a4 += __shfl_xor_sync(0xffffffffu, a4, off);                    \
        a5 += __shfl_xor_sync(0xffffffffu, a5, off);                    \
        a6 += __shfl_xor_sync(0xffffffffu, a6, off);                    \
        a7 += __shfl_xor_sync(0xffffffffu, a7, off);                    \
    } while (0)

// ---- agg1 FUSED with gemm2 --------------------------------------------------
// Gather hs1 from bufA (7 chunks = 50 cols); h1 = relu(dinv*acc + b1) held in
// registers warp-wide; warp GEMM vs W2 (smem); bufB = fp16(dinv * h1@W2).
__global__ __launch_bounds__(256, 6) void k_agg1_fused(
        const float* __restrict__ b1, const float* __restrict__ W2) {
    __shared__ float ws2[HID][64];
    for (int t = threadIdx.x; t < HID * 64; t += 256)
        ws2[t >> 6][t & 63] = W2[t];               // W2 row-major [50][64]
    __syncthreads();

    int node = (blockIdx.x * 256 + threadIdx.x) >> 5;   // 6250 blocks exact
    GATHER_BODY(g_bufA, 7)

    float di = __ldg(g_dinv + node);
    float acc[8] = {a0, a1, a2, a3, a4, a5, a6, a7};
    float v[8];
#pragma unroll
    for (int i = 0; i < 8; i++) {
        int j = q * 8 + i;
        float bv = (j < HID) ? __ldg(b1 + j) : 0.f;
        v[i] = fmaxf(fmaf(di, acc[i], bv), 0.f);    // relu(h1)
    }
    // warp GEMM: lane computes h2[2*lane], h2[2*lane+1]
    float o0 = 0.f, o1 = 0.f;
#pragma unroll
    for (int k = 0; k < HID; k++) {
        float hk = __shfl_sync(0xffffffffu, v[k & 7], k >> 3);
        float2 w = *(const float2*)&ws2[k][2 * lane];
        o0 = fmaf(hk, w.x, o0);
        o1 = fmaf(hk, w.y, o1);
    }
    __half2 hz = __floats2half2_rn(o0 * di, o1 * di);
    *(__half2*)&g_bufB[node * PAD + 2 * lane] = hz;
}

// ---- agg2: gather bufB, z = fp16(dinv*acc + b2) -----------------------------
__global__ __launch_bounds__(256) void k_agg2(const float* __restrict__ b2) {
    int node = (blockIdx.x * 256 + threadIdx.x) >> 5;   // 6250 blocks exact
    GATHER_BODY(g_bufB, 8)

    if (g == 0) {
        float di = g_dinv[node];
        int j0 = q * 8;
        float acc[8] = {a0, a1, a2, a3, a4, a5, a6, a7};
        float v[8];
#pragma unroll
        for (int i = 0; i < 8; i++) {
            float bv = __ldg(b2 + j0 + i);
            v[i] = fmaf(di, acc[i], bv);
        }
        __half2 h0 = __floats2half2_rn(v[0], v[1]);
        __half2 h1 = __floats2half2_rn(v[2], v[3]);
        __half2 h2 = __floats2half2_rn(v[4], v[5]);
        __half2 h3 = __floats2half2_rn(v[6], v[7]);
        uint4 st;
        st.x = *(unsigned*)&h0; st.y = *(unsigned*)&h1;
        st.z = *(unsigned*)&h2; st.w = *(unsigned*)&h3;
        *(uint4*)&g_z[node * PAD + j0] = st;
    }
}

#undef ACCUM
#undef RED
#undef GATHER_BODY

// ---- decode: logits[e] = dot64(z[a], z[b]), z fp16 --------------------------
__global__ void k_decode(const int* __restrict__ pos,
                         const int* __restrict__ neg,
                         float* __restrict__ out) {
    int gt = blockIdx.x * 256 + threadIdx.x;   // 12500 blocks exact
    int e = gt >> 3;
    int j = gt & 7;
    int a, b;
    if (e < EP) { a = pos[e];        b = pos[EP + e]; }
    else        { int e2 = e - EP;  a = neg[e2];     b = neg[EN + e2]; }
    uint4 ua = __ldg((const uint4*)(g_z + a * PAD) + j);
    uint4 ub = __ldg((const uint4*)(g_z + b * PAD) + j);
    __half2* ha = (__half2*)&ua;
    __half2* hb = (__half2*)&ub;
    float s = 0.f;
#pragma unroll
    for (int i = 0; i < 4; i++) {
        float2 fa = __half22float2(ha[i]);
        float2 fb = __half22float2(hb[i]);
        s = fmaf(fa.x, fb.x, s);
        s = fmaf(fa.y, fb.y, s);
    }
#pragma unroll
    for (int o = 4; o; o >>= 1) s += __shfl_xor_sync(0xffffffffu, s, o);
    if (j == 0) out[e] = s;
}

// ---------------------------------------------------------------------------
extern "C" void kernel_launch(void* const* d_in, const int* in_sizes, int n_in,
                              void* d_out, int out_size) {
    const float* x   = (const float*)d_in[0];
    const int*   tr  = (const int*)d_in[1];
    const int*   pos = (const int*)d_in[2];
    const int*   neg = (const int*)d_in[3];
    const float* W1  = (const float*)d_in[4];
    const float* b1  = (const float*)d_in[5];
    const float* W2  = (const float*)d_in[6];
    const float* b2  = (const float*)d_in[7];
    float* out = (float*)d_out;

    const int* src = tr;
    const int* dst = tr + E_TRAIN;

    static cudaStream_t sB = nullptr;
    static cudaEvent_t  evStart = nullptr, evScan = nullptr, evG1 = nullptr;
    if (sB == nullptr) {
        cudaStreamCreateWithFlags(&sB, cudaStreamNonBlocking);
        cudaEventCreateWithFlags(&evStart, cudaEventDisableTiming);
        cudaEventCreateWithFlags(&evScan,  cudaEventDisableTiming);
        cudaEventCreateWithFlags(&evG1,    cudaEventDisableTiming);
    }

    // Fork at t=0: gemm1 (unscaled -> no build dependency) on stream B.
    cudaEventRecord(evStart, 0);
    cudaStreamWaitEvent(sB, evStart, 0);
    k_gemm1<<<(N_NODES + 31) / 32, 256, 0, sB>>>(x, W1);

    // CSR build on default stream, concurrent with gemm1.
    k_zero<<<(N_NODES + 255) / 256, 256>>>();
    k_count<<<(E_TRAIN / 8 + 255) / 256, 256>>>(dst);
    k_scan_local<<<SCAN_NBLK, SCAN_B>>>();
    k_scan_bsum<<<1, 64>>>();
    k_scan_add<<<SCAN_NBLK, SCAN_B>>>();
    cudaEventRecord(evScan, 0);          // dinv ready

    // Stream B: scale bufA by dinv (after gemm1 + scan), concurrent w/ place.
    cudaStreamWaitEvent(sB, evScan, 0);
    k_scale<<<N_NODES * 16 / 256, 256, 0, sB>>>();
    cudaEventRecord(evG1, sB);

    k_place<<<(E_TRAIN / 4 + 255) / 256, 256>>>(src, dst);

    // Join, then fused layer-1 aggregation + gemm2.
    cudaStreamWaitEvent(0, evG1, 0);
    k_agg1_fused<<<N_NODES * 32 / 256, 256>>>(b1, W2);

    // layer-2 aggregation, then decode.
    k_agg2<<<N_NODES * 32 / 256, 256>>>(b2);
    k_decode<<<(EP + EN) * 8 / 256, 256>>>(pos, neg, out);
}

// round 16
// speedup vs baseline: 1.5076x; 1.5076x over previous
#include <cuda_runtime.h>
#include <cuda_fp16.h>

// ---------------------------------------------------------------------------
// GCN link prediction, CSR-gather formulation.
//   layer1: hs1 = dinv*(x@W1) (fp16, scaled by k_scale after gemm1||build)
//   agg1-fused: acc = hs1[c] + sum hs1[src]; h1 = relu(dinv*acc + b1) kept in
//     registers warp-wide; warp-GEMM h2 = h1@W2 (W2 smem + shfl broadcast);
//     bufB = fp16(dinv*h2).   [gemm2 kernel + fp32 bufC eliminated]
//   agg2: acc = bufB[c] + sum bufB[src]; z = fp16(dinv*acc + b2)
//   decode: dot64 over fp16 z.
// R15 lesson: NO min-blocks launch_bounds on the fused kernel (it forced
// spills into the gather loop); unroll-2 gather there to keep regs ~<52.
// ---------------------------------------------------------------------------

#define N_NODES 50000
#define E_TRAIN 1600000
#define EP      200000
#define EN      200000
#define F_IN    50
#define HID     50
#define DOUT    64
#define PAD     64

#define SCAN_B  1024
#define SCAN_NBLK ((N_NODES + SCAN_B - 1) / SCAN_B)   // 49

__device__ __align__(256) __half g_bufA[N_NODES * PAD]; // hs1 fp16
__device__ __align__(256) __half g_bufB[N_NODES * PAD]; // hs2 fp16
__device__ __align__(256) __half g_z[N_NODES * PAD];    // final z (fp16)
__device__ int   g_deg[N_NODES];
__device__ int   g_rowptr[N_NODES + 1];
__device__ int   g_bsum[SCAN_NBLK];
__device__ int   g_boff[SCAN_NBLK];
__device__ __align__(16) unsigned short g_rank[E_TRAIN];
__device__ __align__(16) unsigned short g_esrc[E_TRAIN];
__device__ float g_dinv[N_NODES];

// ---- degree + rank ----------------------------------------------------------
__global__ void k_zero() {
    int i = blockIdx.x * blockDim.x + threadIdx.x;
    if (i < N_NODES) g_deg[i] = 0;
}

__global__ void k_count(const int* __restrict__ dst) {
    int t = blockIdx.x * 256 + threadIdx.x;
    if (t < E_TRAIN / 8) {
        int4 d0 = __ldg((const int4*)dst + 2 * t);
        int4 d1 = __ldg((const int4*)dst + 2 * t + 1);
        unsigned r0 = atomicAdd(&g_deg[d0.x], 1);
        unsigned r1 = atomicAdd(&g_deg[d0.y], 1);
        unsigned r2 = atomicAdd(&g_deg[d0.z], 1);
        unsigned r3 = atomicAdd(&g_deg[d0.w], 1);
        unsigned r4 = atomicAdd(&g_deg[d1.x], 1);
        unsigned r5 = atomicAdd(&g_deg[d1.y], 1);
        unsigned r6 = atomicAdd(&g_deg[d1.z], 1);
        unsigned r7 = atomicAdd(&g_deg[d1.w], 1);
        uint4 pk;
        pk.x = r0 | (r1 << 16);
        pk.y = r2 | (r3 << 16);
        pk.z = r4 | (r5 << 16);
        pk.w = r6 | (r7 << 16);
        ((uint4*)g_rank)[t] = pk;
    }
}

// ---- 3-phase multi-block exclusive scan -> rowptr/dinv ----------------------
__global__ __launch_bounds__(SCAN_B) void k_scan_local() {
    __shared__ int sh[SCAN_B];
    int t = threadIdx.x;
    int gid = blockIdx.x * SCAN_B + t;
    int d = (gid < N_NODES) ? g_deg[gid] : 0;
    int val = d;
    sh[t] = val;
    __syncthreads();
    for (int off = 1; off < SCAN_B; off <<= 1) {
        int v = (t >= off) ? sh[t - off] : 0;
        __syncthreads();
        val += v;
        sh[t] = val;
        __syncthreads();
    }
    if (gid < N_NODES) {
        g_rowptr[gid] = val - d;
        g_dinv[gid]   = rsqrtf((float)(d + 1));  // +1 self loop
    }
    if (t == SCAN_B - 1) g_bsum[blockIdx.x] = val;
}

__global__ void k_scan_bsum() {
    __shared__ int sh[SCAN_NBLK];
    int t = threadIdx.x;   // 64 threads
    if (t < SCAN_NBLK) sh[t] = g_bsum[t];
    __syncthreads();
    if (t == 0) {
        int run = 0;
#pragma unroll
        for (int i = 0; i < SCAN_NBLK; i++) {
            int d = sh[i];
            sh[i] = run;
            run += d;
        }
        g_rowptr[N_NODES] = run;
    }
    __syncthreads();
    if (t < SCAN_NBLK) g_boff[t] = sh[t];
}

__global__ __launch_bounds__(SCAN_B) void k_scan_add() {
    int gid = blockIdx.x * SCAN_B + threadIdx.x;
    if (gid < N_NODES) g_rowptr[gid] += __ldg(g_boff + blockIdx.x);
}

// ---- atomic-free placement (4 edges/thread) ---------------------------------
__global__ void k_place(const int* __restrict__ src, const int* __restrict__ dst) {
    int t = blockIdx.x * 256 + threadIdx.x;
    if (t < E_TRAIN / 4) {
        int4 s0 = __ldg((const int4*)src + t);
        int4 d0 = __ldg((const int4*)dst + t);
        uint2 pk = __ldg((const uint2*)g_rank + t);
        int p0 = __ldg(g_rowptr + d0.x) + (pk.x & 0xffff);
        int p1 = __ldg(g_rowptr + d0.y) + (pk.x >> 16);
        int p2 = __ldg(g_rowptr + d0.z) + (pk.y & 0xffff);
        int p3 = __ldg(g_rowptr + d0.w) + (pk.y >> 16);
        g_esrc[p0] = (unsigned short)s0.x;
        g_esrc[p1] = (unsigned short)s0.y;
        g_esrc[p2] = (unsigned short)s0.z;
        g_esrc[p3] = (unsigned short)s0.w;
    }
}

// ---- scale bufA rows by dinv (layer 1) --------------------------------------
__global__ __launch_bounds__(256) void k_scale() {
    int t = blockIdx.x * 256 + threadIdx.x;   // 3125 blocks exact
    int node = t >> 4, q = t & 15;
    float di = __ldg(g_dinv + node);
    uint2 u = *(uint2*)&g_bufA[node * PAD + q * 4];
    __half2* hp = (__half2*)&u;
    float2 f0 = __half22float2(hp[0]);
    float2 f1 = __half22float2(hp[1]);
    __half2 o0 = __floats2half2_rn(f0.x * di, f0.y * di);
    __half2 o1 = __floats2half2_rn(f1.x * di, f1.y * di);
    uint2 st; st.x = *(unsigned*)&o0; st.y = *(unsigned*)&o1;
    *(uint2*)&g_bufA[node * PAD + q * 4] = st;
}

// ---- GEMM 1: bufA = fp16(x @ W1) UNSCALED, 32 nodes/block -------------------
__global__ __launch_bounds__(256) void k_gemm1(const float* __restrict__ x,
                                               const float* __restrict__ W1) {
    __shared__ float ws[F_IN][64];
    __shared__ float xs[32][F_IN + 2];
    int tid = threadIdx.x;
    int nodeBase = blockIdx.x * 32;
    for (int t = tid; t < F_IN * 64; t += 256) {
        int k = t >> 6, j = t & 63;
        ws[k][j] = (j < HID) ? W1[k * HID + j] : 0.f;
    }
    for (int t = tid; t < 32 * F_IN; t += 256) {
        int n = t / F_IN, k = t % F_IN;
        int node = nodeBase + n;
        xs[n][k] = (node < N_NODES) ? x[node * F_IN + k] : 0.f;
    }
    __syncthreads();
    int n = tid >> 4, jq = tid & 15;
    int node0 = nodeBase + n;
    int node1 = nodeBase + n + 16;
    float4 accA = make_float4(0.f, 0.f, 0.f, 0.f);
    float4 accB = make_float4(0.f, 0.f, 0.f, 0.f);
#pragma unroll
    for (int k = 0; k < F_IN; k++) {
        float4 w = *(const float4*)&ws[k][jq * 4];
        float xv0 = xs[n][k];
        float xv1 = xs[n + 16][k];
        accA.x = fmaf(xv0, w.x, accA.x);
        accA.y = fmaf(xv0, w.y, accA.y);
        accA.z = fmaf(xv0, w.z, accA.z);
        accA.w = fmaf(xv0, w.w, accA.w);
        accB.x = fmaf(xv1, w.x, accB.x);
        accB.y = fmaf(xv1, w.y, accB.y);
        accB.z = fmaf(xv1, w.z, accB.z);
        accB.w = fmaf(xv1, w.w, accB.w);
    }
    if (node0 < N_NODES) {
        __half2 p0 = __floats2half2_rn(accA.x, accA.y);
        __half2 p1 = __floats2half2_rn(accA.z, accA.w);
        uint2 st; st.x = *(unsigned*)&p0; st.y = *(unsigned*)&p1;
        *(uint2*)&g_bufA[node0 * PAD + jq * 4] = st;
    }
    if (node1 < N_NODES) {
        __half2 p0 = __floats2half2_rn(accB.x, accB.y);
        __half2 p1 = __floats2half2_rn(accB.z, accB.w);
        uint2 st; st.x = *(unsigned*)&p0; st.y = *(unsigned*)&p1;
        *(uint2*)&g_bufA[node1 * PAD + jq * 4] = st;
    }
}

// ---- shared ACCUM/RED helpers ----------------------------------------------
#define ACCUM(U) do {                                                   \
        __half2* hp = (__half2*)&(U);                                   \
        float2 f0 = __half22float2(hp[0]);                              \
        float2 f1 = __half22float2(hp[1]);                              \
        float2 f2 = __half22float2(hp[2]);                              \
        float2 f3 = __half22float2(hp[3]);                              \
        a0 += f0.x; a1 += f0.y; a2 += f1.x; a3 += f1.y;                 \
        a4 += f2.x; a5 += f2.y; a6 += f3.x; a7 += f3.y;                 \
    } while (0)

#define RED(off) do {                                                   \
        a0 += __shfl_xor_sync(0xffffffffu, a0, off);                    \
        a1 += __shfl_xor_sync(0xffffffffu, a1, off);                    \
        a2 += __shfl_xor_sync(0xffffffffu, a2, off);                    \
        a3 += __shfl_xor_sync(0xffffffffu, a3, off);                    \
        a4 += __shfl_xor_sync(0xffffffffu, a4, off);                    \
        a5 += __shfl_xor_sync(0xffffffffu, a5, off);                    \
        a6 += __shfl_xor_sync(0xffffffffu, a6, off);                    \
        a7 += __shfl_xor_sync(0xffffffffu, a7, off);                    \
    } while (0)

// ---- agg1 FUSED with gemm2 (unroll-2 gather, no min-blocks bound) -----------
__global__ __launch_bounds__(256) void k_agg1_fused(
        const float* __restrict__ b1, const float* __restrict__ W2) {
    __shared__ float ws2[HID][64];
    for (int t = threadIdx.x; t < HID * 64; t += 256)
        ws2[t >> 6][t & 63] = W2[t];               // W2 row-major [50][64]
    __syncthreads();

    int node = (blockIdx.x * 256 + threadIdx.x) >> 5;   // 6250 blocks exact
    int lane = threadIdx.x & 31;
    int g = lane >> 3, q = lane & 7;
    int rp = g_rowptr[node], re = g_rowptr[node + 1];
    float a0 = 0.f, a1 = 0.f, a2 = 0.f, a3 = 0.f;
    float a4 = 0.f, a5 = 0.f, a6 = 0.f, a7 = 0.f;
    const uint4* rows = (const uint4*)g_bufA;
    const bool act = (q < 7);                          // 50 cols = 7 chunks

    if (g == 0 && act) {                               // self loop
        uint4 u = __ldg(rows + node * 8 + q);
        ACCUM(u);
    }
    int e = rp + g;
    for (; e + 4 < re; e += 8) {                       // unroll-2: 8 regs staging
        int s0 = (int)__ldg(g_esrc + e);
        int s1 = (int)__ldg(g_esrc + e + 4);
        if (act) {
            uint4 u0 = __ldg(rows + s0 * 8 + q);
            uint4 u1 = __ldg(rows + s1 * 8 + q);
            ACCUM(u0); ACCUM(u1);
        }
    }
    if (e < re) {
        int s0 = (int)__ldg(g_esrc + e);
        if (act) {
            uint4 u0 = __ldg(rows + s0 * 8 + q);
            ACCUM(u0);
        }
    }
    RED(8);
    RED(16);
    // now every lane holds full reduced sums for its chunk q
    float di = __ldg(g_dinv + node);
    float acc[8] = {a0, a1, a2, a3, a4, a5, a6, a7};
    float v[8];
#pragma unroll
    for (int i = 0; i < 8; i++) {
        int j = q * 8 + i;
        float bv = (j < HID) ? __ldg(b1 + j) : 0.f;
        v[i] = fmaxf(fmaf(di, acc[i], bv), 0.f);       // relu(h1), 0 for j>=50
    }
    // warp GEMM: lane computes h2[2*lane], h2[2*lane+1]
    float o0 = 0.f, o1 = 0.f;
#pragma unroll
    for (int k = 0; k < HID; k++) {
        float hk = __shfl_sync(0xffffffffu, v[k & 7], k >> 3);
        float2 w = *(const float2*)&ws2[k][2 * lane];
        o0 = fmaf(hk, w.x, o0);
        o1 = fmaf(hk, w.y, o1);
    }
    __half2 hz = __floats2half2_rn(o0 * di, o1 * di);
    *(__half2*)&g_bufB[node * PAD + 2 * lane] = hz;
}

// ---- agg2: gather bufB (unroll-4), z = fp16(dinv*acc + b2) ------------------
__global__ __launch_bounds__(256) void k_agg2(const float* __restrict__ b2) {
    int node = (blockIdx.x * 256 + threadIdx.x) >> 5;   // 6250 blocks exact
    int lane = threadIdx.x & 31;
    int g = lane >> 3, q = lane & 7;
    int rp = g_rowptr[node], re = g_rowptr[node + 1];
    float a0 = 0.f, a1 = 0.f, a2 = 0.f, a3 = 0.f;
    float a4 = 0.f, a5 = 0.f, a6 = 0.f, a7 = 0.f;
    const uint4* rows = (const uint4*)g_bufB;

    if (g == 0) {                                       // self loop
        uint4 u = __ldg(rows + node * 8 + q);
        ACCUM(u);
    }
    int e = rp + g;
    for (; e + 12 < re; e += 16) {
        int s0 = (int)__ldg(g_esrc + e);
        int s1 = (int)__ldg(g_esrc + e + 4);
        int s2 = (int)__ldg(g_esrc + e + 8);
        int s3 = (int)__ldg(g_esrc + e + 12);
        uint4 u0 = __ldg(rows + s0 * 8 + q);
        uint4 u1 = __ldg(rows + s1 * 8 + q);
        uint4 u2 = __ldg(rows + s2 * 8 + q);
        uint4 u3 = __ldg(rows + s3 * 8 + q);
        ACCUM(u0); ACCUM(u1); ACCUM(u2); ACCUM(u3);
    }
    for (; e + 4 < re; e += 8) {
        int s0 = (int)__ldg(g_esrc + e);
        int s1 = (int)__ldg(g_esrc + e + 4);
        uint4 u0 = __ldg(rows + s0 * 8 + q);
        uint4 u1 = __ldg(rows + s1 * 8 + q);
        ACCUM(u0); ACCUM(u1);
    }
    if (e < re) {
        int s0 = (int)__ldg(g_esrc + e);
        uint4 u0 = __ldg(rows + s0 * 8 + q);
        ACCUM(u0);
    }
    RED(8);
    RED(16);

    if (g == 0) {
        float di = g_dinv[node];
        int j0 = q * 8;
        float acc[8] = {a0, a1, a2, a3, a4, a5, a6, a7};
        float v[8];
#pragma unroll
        for (int i = 0; i < 8; i++) {
            float bv = __ldg(b2 + j0 + i);
            v[i] = fmaf(di, acc[i], bv);
        }
        __half2 h0 = __floats2half2_rn(v[0], v[1]);
        __half2 h1 = __floats2half2_rn(v[2], v[3]);
        __half2 h2 = __floats2half2_rn(v[4], v[5]);
        __half2 h3 = __floats2half2_rn(v[6], v[7]);
        uint4 st;
        st.x = *(unsigned*)&h0; st.y = *(unsigned*)&h1;
        st.z = *(unsigned*)&h2; st.w = *(unsigned*)&h3;
        *(uint4*)&g_z[node * PAD + j0] = st;
    }
}

#undef ACCUM
#undef RED

// ---- decode: logits[e] = dot64(z[a], z[b]), z fp16 --------------------------
__global__ void k_decode(const int* __restrict__ pos,
                         const int* __restrict__ neg,
                         float* __restrict__ out) {
    int gt = blockIdx.x * 256 + threadIdx.x;   // 12500 blocks exact
    int e = gt >> 3;
    int j = gt & 7;
    int a, b;
    if (e < EP) { a = pos[e];        b = pos[EP + e]; }
    else        { int e2 = e - EP;  a = neg[e2];     b = neg[EN + e2]; }
    uint4 ua = __ldg((const uint4*)(g_z + a * PAD) + j);
    uint4 ub = __ldg((const uint4*)(g_z + b * PAD) + j);
    __half2* ha = (__half2*)&ua;
    __half2* hb = (__half2*)&ub;
    float s = 0.f;
#pragma unroll
    for (int i = 0; i < 4; i++) {
        float2 fa = __half22float2(ha[i]);
        float2 fb = __half22float2(hb[i]);
        s = fmaf(fa.x, fb.x, s);
        s = fmaf(fa.y, fb.y, s);
    }
#pragma unroll
    for (int o = 4; o; o >>= 1) s += __shfl_xor_sync(0xffffffffu, s, o);
    if (j == 0) out[e] = s;
}

// ---------------------------------------------------------------------------
extern "C" void kernel_launch(void* const* d_in, const int* in_sizes, int n_in,
                              void* d_out, int out_size) {
    const float* x   = (const float*)d_in[0];
    const int*   tr  = (const int*)d_in[1];
    const int*   pos = (const int*)d_in[2];
    const int*   neg = (const int*)d_in[3];
    const float* W1  = (const float*)d_in[4];
    const float* b1  = (const float*)d_in[5];
    const float* W2  = (const float*)d_in[6];
    const float* b2  = (const float*)d_in[7];
    float* out = (float*)d_out;

    const int* src = tr;
    const int* dst = tr + E_TRAIN;

    static cudaStream_t sB = nullptr;
    static cudaEvent_t  evStart = nullptr, evScan = nullptr, evG1 = nullptr;
    if (sB == nullptr) {
        cudaStreamCreateWithFlags(&sB, cudaStreamNonBlocking);
        cudaEventCreateWithFlags(&evStart, cudaEventDisableTiming);
        cudaEventCreateWithFlags(&evScan,  cudaEventDisableTiming);
        cudaEventCreateWithFlags(&evG1,    cudaEventDisableTiming);
    }

    // Fork at t=0: gemm1 (unscaled -> no build dependency) on stream B.
    cudaEventRecord(evStart, 0);
    cudaStreamWaitEvent(sB, evStart, 0);
    k_gemm1<<<(N_NODES + 31) / 32, 256, 0, sB>>>(x, W1);

    // CSR build on default stream, concurrent with gemm1.
    k_zero<<<(N_NODES + 255) / 256, 256>>>();
    k_count<<<(E_TRAIN / 8 + 255) / 256, 256>>>(dst);
    k_scan_local<<<SCAN_NBLK, SCAN_B>>>();
    k_scan_bsum<<<1, 64>>>();
    k_scan_add<<<SCAN_NBLK, SCAN_B>>>();
    cudaEventRecord(evScan, 0);          // dinv ready

    // Stream B: scale bufA by dinv (after gemm1 + scan), concurrent w/ place.
    cudaStreamWaitEvent(sB, evScan, 0);
    k_scale<<<N_NODES * 16 / 256, 256, 0, sB>>>();
    cudaEventRecord(evG1, sB);

    k_place<<<(E_TRAIN / 4 + 255) / 256, 256>>>(src, dst);

    // Join, then fused layer-1 aggregation + gemm2.
    cudaStreamWaitEvent(0, evG1, 0);
    k_agg1_fused<<<N_NODES * 32 / 256, 256>>>(b1, W2);

    // layer-2 aggregation, then decode.
    k_agg2<<<N_NODES * 32 / 256, 256>>>(b2);
    k_decode<<<(EP + EN) * 8 / 256, 256>>>(pos, neg, out);
}